// round 16
// baseline (speedup 1.0000x reference)
#include <cuda_runtime.h>
#include <cuda_fp16.h>
#include <cstdint>

// Problem constants: N=100000, F=16, E=3200000, H=64
#define NN 100000
#define FF 16
#define EE 3200000
#define HH 64
#define NGROUPS (EE / 16)     // 200000 warp-groups of 16 edges, exact

// fp16 copy of x: one 32B row (16 halves) per node = 2 uint4.
__device__ uint4 g_Xh[(size_t)NN * 2];   // 3.2 MB

// ---------------------------------------------------------------------------
// Kernel 1: fp16 copy of x (one uint4 = 8 halves per thread).
// ---------------------------------------------------------------------------
__global__ void __launch_bounds__(256)
convert_kernel(const float* __restrict__ x)
{
    int idx = blockIdx.x * blockDim.x + threadIdx.x;
    if (idx >= NN * 2) return;
    const float4* x4 = (const float4*)x;
    float4 lo = x4[idx * 2];
    float4 hi = x4[idx * 2 + 1];
    __half2 h0 = __floats2half2_rn(lo.x, lo.y);
    __half2 h1 = __floats2half2_rn(lo.z, lo.w);
    __half2 h2 = __floats2half2_rn(hi.x, hi.y);
    __half2 h3 = __floats2half2_rn(hi.z, hi.w);
    uint4 o;
    o.x = *(uint32_t*)&h0; o.y = *(uint32_t*)&h1;
    o.z = *(uint32_t*)&h2; o.w = *(uint32_t*)&h3;
    g_Xh[idx] = o;
}

// ---------------------------------------------------------------------------
// HMMA m16n8k16 row.col f32.f16.f16.f32
// ---------------------------------------------------------------------------
__device__ __forceinline__ void hmma(float* cc, uint32_t a0, uint32_t a1,
                                     uint32_t a2, uint32_t a3,
                                     uint32_t b0, uint32_t b1) {
    asm volatile(
        "mma.sync.aligned.m16n8k16.row.col.f32.f16.f16.f32 "
        "{%0,%1,%2,%3}, {%4,%5,%6,%7}, {%8,%9}, {%0,%1,%2,%3};"
        : "+f"(cc[0]), "+f"(cc[1]), "+f"(cc[2]), "+f"(cc[3])
        : "r"(a0), "r"(a1), "r"(a2), "r"(a3), "r"(b0), "r"(b1));
}

// ---------------------------------------------------------------------------
// Kernel 2: per-warp tensor-core edge kernel (persistent, grid-stride).
// Warp iteration = 16 consecutive edges:
//   A[16,32] fp16 = [x_dst | x_src] rows, fragments loaded straight from g_Xh
//   B[32,64]      = W1 fp16, held in registers (loaded once per block)
//   D[16,64] f32  = A @ B via 16x mma.sync (8 N-tiles x 2 K-steps)
//   a,b = W2^T relu(D + b1);  out = a*(x_dst - b*x_src)
// ---------------------------------------------------------------------------
__global__ void __launch_bounds__(128)
edge_mma_kernel(const int* __restrict__ ei,      // [2,E] int32: src row, dst row
                const float* __restrict__ W1,    // [32,64]
                const float* __restrict__ b1,    // [64]
                const float* __restrict__ W2,    // [64,2]
                const float* __restrict__ b2,    // [2]
                float* __restrict__ out)         // [E,16]
{
    __shared__ float4 tbl[HH];     // (b1[j], wa[j], wb[j], 0)
    const int tid  = threadIdx.x;
    const int wid  = tid >> 5;
    const int lane = tid & 31;
    if (tid < HH)
        tbl[tid] = make_float4(b1[tid], W2[2 * tid], W2[2 * tid + 1], 0.0f);
    __syncthreads();

    const int gq = lane >> 2;      // group id (row within m16: gq and gq+8)
    const int c  = lane & 3;

    // ---- B fragments (col-major k16n8): held in registers per thread ----
    // bf[nt][ks][r]: n-tile nt (cols 8nt..8nt+7), k-step ks (k = 16ks..16ks+15)
    uint32_t bf[8][2][2];
#pragma unroll
    for (int nt = 0; nt < 8; nt++) {
        int j = 8 * nt + gq;
#pragma unroll
        for (int ks = 0; ks < 2; ks++) {
            int k0 = ks * 16 + 2 * c;
            __half2 lo = __floats2half2_rn(W1[k0 * HH + j], W1[(k0 + 1) * HH + j]);
            __half2 hi = __floats2half2_rn(W1[(k0 + 8) * HH + j], W1[(k0 + 9) * HH + j]);
            bf[nt][ks][0] = *(uint32_t*)&lo;
            bf[nt][ks][1] = *(uint32_t*)&hi;
        }
    }
    const float2 b2v = *(const float2*)b2;

    const unsigned FULL = 0xffffffffu;
    const int wstep = gridDim.x * 4;

    for (int g = blockIdx.x * 4 + wid; g < NGROUPS; g += wstep) {
        const int ebase = g * 16;
        // rows gq (edge e0) and gq+8 (edge e1) of this warp's 16-edge tile
        const int e0 = ebase + gq;
        const int e1 = e0 + 8;
        int s0 = ei[e0], d0 = ei[EE + e0];
        int s1 = ei[e1], d1 = ei[EE + e1];

        float acc[8][4];
#pragma unroll
        for (int nt = 0; nt < 8; nt++) {
            acc[nt][0] = 0.0f; acc[nt][1] = 0.0f;
            acc[nt][2] = 0.0f; acc[nt][3] = 0.0f;
        }

        // ---- K-step 0: A cols 0..15 = x_dst halves (words c, c+4 of row) ----
        {
            const uint32_t* r0 = (const uint32_t*)(g_Xh + d0 * 2);
            const uint32_t* r1 = (const uint32_t*)(g_Xh + d1 * 2);
            uint32_t a0 = r0[c], a2 = r0[c + 4];
            uint32_t a1 = r1[c], a3 = r1[c + 4];
#pragma unroll
            for (int nt = 0; nt < 8; nt++)
                hmma(acc[nt], a0, a1, a2, a3, bf[nt][0][0], bf[nt][0][1]);
        }
        // ---- K-step 1: A cols 16..31 = x_src halves ----
        {
            const uint32_t* r0 = (const uint32_t*)(g_Xh + s0 * 2);
            const uint32_t* r1 = (const uint32_t*)(g_Xh + s1 * 2);
            uint32_t a0 = r0[c], a2 = r0[c + 4];
            uint32_t a1 = r1[c], a3 = r1[c + 4];
#pragma unroll
            for (int nt = 0; nt < 8; nt++)
                hmma(acc[nt], a0, a1, a2, a3, bf[nt][1][0], bf[nt][1][1]);
        }

        // ---- epilogue partials: rows e0 (acc[.][0,1]) and e1 (acc[.][2,3]),
        //      thread's cols j = 8nt + 2c, 8nt + 2c + 1 ----
        float pa0 = 0.0f, pb0 = 0.0f, pa1 = 0.0f, pb1 = 0.0f;
#pragma unroll
        for (int nt = 0; nt < 8; nt++) {
            float4 t0 = tbl[8 * nt + 2 * c];
            float4 t1 = tbl[8 * nt + 2 * c + 1];
            float h;
            h = fmaxf(acc[nt][0] + t0.x, 0.0f);
            pa0 = fmaf(h, t0.y, pa0); pb0 = fmaf(h, t0.z, pb0);
            h = fmaxf(acc[nt][1] + t1.x, 0.0f);
            pa0 = fmaf(h, t1.y, pa0); pb0 = fmaf(h, t1.z, pb0);
            h = fmaxf(acc[nt][2] + t0.x, 0.0f);
            pa1 = fmaf(h, t0.y, pa1); pb1 = fmaf(h, t0.z, pb1);
            h = fmaxf(acc[nt][3] + t1.x, 0.0f);
            pa1 = fmaf(h, t1.y, pa1); pb1 = fmaf(h, t1.z, pb1);
        }
        // reduce over the 4 lanes of each quad (cols split 4 ways)
        pa0 += __shfl_xor_sync(FULL, pa0, 1); pa0 += __shfl_xor_sync(FULL, pa0, 2);
        pb0 += __shfl_xor_sync(FULL, pb0, 1); pb0 += __shfl_xor_sync(FULL, pb0, 2);
        pa1 += __shfl_xor_sync(FULL, pa1, 1); pa1 += __shfl_xor_sync(FULL, pa1, 2);
        pb1 += __shfl_xor_sync(FULL, pb1, 1); pb1 += __shfl_xor_sync(FULL, pb1, 2);
        pa0 += b2v.x; pb0 += b2v.y;
        pa1 += b2v.x; pb1 += b2v.y;

        // ---- exchange: writer lane L handles edge ebase + L/2 ----
        // edge r (0..7) lives in quad r as (pa0,pb0,d0,s0); edge r+8 as *1.
        const int  srcl = ((lane >> 1) & 7) * 4;
        const bool hiE  = (lane >= 16);
        float aA = __shfl_sync(FULL, pa0, srcl), aB = __shfl_sync(FULL, pa1, srcl);
        float bA = __shfl_sync(FULL, pb0, srcl), bB = __shfl_sync(FULL, pb1, srcl);
        int   dA = __shfl_sync(FULL, d0,  srcl), dB = __shfl_sync(FULL, d1,  srcl);
        int   sA = __shfl_sync(FULL, s0,  srcl), sB = __shfl_sync(FULL, s1,  srcl);
        float a = hiE ? aB : aA;
        float b = hiE ? bB : bA;
        int   d = hiE ? dB : dA;
        int   s = hiE ? sB : sA;

        const int e    = ebase + (lane >> 1);
        const int half = lane & 1;            // which 8 floats of the 16
        uint4 xdw = g_Xh[d * 2 + half];
        uint4 xsw = g_Xh[s * 2 + half];
        float2 xd0 = __half22float2(*(__half2*)&xdw.x);
        float2 xd1 = __half22float2(*(__half2*)&xdw.y);
        float2 xd2 = __half22float2(*(__half2*)&xdw.z);
        float2 xd3 = __half22float2(*(__half2*)&xdw.w);
        float2 xs0 = __half22float2(*(__half2*)&xsw.x);
        float2 xs1 = __half22float2(*(__half2*)&xsw.y);
        float2 xs2 = __half22float2(*(__half2*)&xsw.z);
        float2 xs3 = __half22float2(*(__half2*)&xsw.w);

        float* op = out + (size_t)e * FF + half * 8;
        float4 o;
        o.x = a * (xd0.x - b * xs0.x);
        o.y = a * (xd0.y - b * xs0.y);
        o.z = a * (xd1.x - b * xs1.x);
        o.w = a * (xd1.y - b * xs1.y);
        ((float4*)op)[0] = o;
        o.x = a * (xd2.x - b * xs2.x);
        o.y = a * (xd2.y - b * xs2.y);
        o.z = a * (xd3.x - b * xs3.x);
        o.w = a * (xd3.y - b * xs3.y);
        ((float4*)op)[1] = o;
    }
}

// ---------------------------------------------------------------------------
// Launch
// ---------------------------------------------------------------------------
extern "C" void kernel_launch(void* const* d_in, const int* in_sizes, int n_in,
                              void* d_out, int out_size)
{
    const float* x   = (const float*)d_in[0];   // [N,16]
    const int*   ei  = (const int*)d_in[1];     // [2,E] int32
    const float* W1  = (const float*)d_in[2];   // [32,64]
    const float* b1  = (const float*)d_in[3];   // [64]
    const float* W2  = (const float*)d_in[4];   // [64,2]
    const float* b2  = (const float*)d_in[5];   // [2]
    float*       out = (float*)d_out;           // [E,16]

    (void)in_sizes; (void)n_in; (void)out_size;

    convert_kernel<<<(NN * 2 + 255) / 256, 256>>>(x);
    edge_mma_kernel<<<1480, 128>>>(ei, W1, b1, W2, b2, out);
}

// round 17
// speedup vs baseline: 1.0276x; 1.0276x over previous
#include <cuda_runtime.h>
#include <cuda_fp16.h>
#include <cstdint>

// Problem constants: N=100000, F=16, E=3200000, H=64
#define NN 100000
#define FF 16
#define EE 3200000
#define HH 64
#define NGROUPS (EE / 16)     // 200000 warp-groups of 16 edges, exact
#define GRID_MMA 1480

// fp16 copy of x: one 32B row (16 halves) per node = 2 uint4.
__device__ uint4 g_Xh[(size_t)NN * 2];   // 3.2 MB

// ---------------------------------------------------------------------------
// Kernel 1: fp16 copy of x (one uint4 = 8 halves per thread).
// ---------------------------------------------------------------------------
__global__ void __launch_bounds__(256)
convert_kernel(const float* __restrict__ x)
{
    int idx = blockIdx.x * blockDim.x + threadIdx.x;
    if (idx >= NN * 2) return;
    const float4* x4 = (const float4*)x;
    float4 lo = x4[idx * 2];
    float4 hi = x4[idx * 2 + 1];
    __half2 h0 = __floats2half2_rn(lo.x, lo.y);
    __half2 h1 = __floats2half2_rn(lo.z, lo.w);
    __half2 h2 = __floats2half2_rn(hi.x, hi.y);
    __half2 h3 = __floats2half2_rn(hi.z, hi.w);
    uint4 o;
    o.x = *(uint32_t*)&h0; o.y = *(uint32_t*)&h1;
    o.z = *(uint32_t*)&h2; o.w = *(uint32_t*)&h3;
    g_Xh[idx] = o;
}

// ---------------------------------------------------------------------------
// HMMA m16n8k16 row.col f32.f16.f16.f32
// ---------------------------------------------------------------------------
__device__ __forceinline__ void hmma(float* cc, uint32_t a0, uint32_t a1,
                                     uint32_t a2, uint32_t a3,
                                     uint32_t b0, uint32_t b1) {
    asm volatile(
        "mma.sync.aligned.m16n8k16.row.col.f32.f16.f16.f32 "
        "{%0,%1,%2,%3}, {%4,%5,%6,%7}, {%8,%9}, {%0,%1,%2,%3};"
        : "+f"(cc[0]), "+f"(cc[1]), "+f"(cc[2]), "+f"(cc[3])
        : "r"(a0), "r"(a1), "r"(a2), "r"(a3), "r"(b0), "r"(b1));
}

// ---------------------------------------------------------------------------
// Kernel 2: per-warp tensor-core edge kernel (persistent).
// Warp iteration = 16 consecutive edges. Changes vs R16:
//  - per-nt accumulator consumed immediately (acc = 4 regs, not 32)
//  - epilogue uses the A-fragment registers directly (quad already holds
//    both (a,b) coefficients and the fp16 x halves it must write) ->
//    no x reloads, no exchange shuffles
//  - __launch_bounds__(128, 8) pins regs <= 64 for 50% occupancy
// ---------------------------------------------------------------------------
__global__ void __launch_bounds__(128, 8)
edge_mma_kernel(const int* __restrict__ ei,      // [2,E] int32: src row, dst row
                const float* __restrict__ W1,    // [32,64]
                const float* __restrict__ b1,    // [64]
                const float* __restrict__ W2,    // [64,2]
                const float* __restrict__ b2,    // [2]
                float* __restrict__ out)         // [E,16]
{
    __shared__ float4 tbl[HH];     // (b1[j], wa[j], wb[j], 0)
    const int tid  = threadIdx.x;
    const int wid  = tid >> 5;
    const int lane = tid & 31;
    if (tid < HH)
        tbl[tid] = make_float4(b1[tid], W2[2 * tid], W2[2 * tid + 1], 0.0f);
    __syncthreads();

    const int gq = lane >> 2;      // quad id = row pair (gq, gq+8) in m16
    const int c  = lane & 3;

    // ---- B fragments (col-major k16n8), held in registers ----
    uint32_t bf[8][2][2];
#pragma unroll
    for (int nt = 0; nt < 8; nt++) {
        int j = 8 * nt + gq;
#pragma unroll
        for (int ks = 0; ks < 2; ks++) {
            int k0 = ks * 16 + 2 * c;
            __half2 lo = __floats2half2_rn(W1[k0 * HH + j], W1[(k0 + 1) * HH + j]);
            __half2 hi = __floats2half2_rn(W1[(k0 + 8) * HH + j], W1[(k0 + 9) * HH + j]);
            bf[nt][ks][0] = *(uint32_t*)&lo;
            bf[nt][ks][1] = *(uint32_t*)&hi;
        }
    }
    const float2 b2v = *(const float2*)b2;

    const unsigned FULL = 0xffffffffu;
    const int wstep = gridDim.x * 4;

    for (int g = blockIdx.x * 4 + wid; g < NGROUPS; g += wstep) {
        const int ebase = g * 16;
        const int e0 = ebase + gq;       // row gq
        const int e1 = e0 + 8;           // row gq+8
        int s0 = ei[e0], d0 = ei[EE + e0];
        int s1 = ei[e1], d1 = ei[EE + e1];

        // ---- A fragments: k-step0 = x_dst, k-step1 = x_src ----
        const uint32_t* rd0 = (const uint32_t*)(g_Xh + d0 * 2);
        const uint32_t* rd1 = (const uint32_t*)(g_Xh + d1 * 2);
        const uint32_t* rs0 = (const uint32_t*)(g_Xh + s0 * 2);
        const uint32_t* rs1 = (const uint32_t*)(g_Xh + s1 * 2);
        uint32_t ad0 = rd0[c], ad2 = rd0[c + 4];   // e0: halves 2c,2c+1 | 8+2c,8+2c+1
        uint32_t ad1 = rd1[c], ad3 = rd1[c + 4];   // e1: same cols
        uint32_t as0 = rs0[c], as2 = rs0[c + 4];
        uint32_t as1 = rs1[c], as3 = rs1[c + 4];

        // ---- n-tile loop: MMA pair then immediate relu + W2 partials ----
        float pa0 = 0.0f, pb0 = 0.0f, pa1 = 0.0f, pb1 = 0.0f;
#pragma unroll
        for (int nt = 0; nt < 8; nt++) {
            float acc[4] = {0.0f, 0.0f, 0.0f, 0.0f};
            hmma(acc, ad0, ad1, ad2, ad3, bf[nt][0][0], bf[nt][0][1]);
            hmma(acc, as0, as1, as2, as3, bf[nt][1][0], bf[nt][1][1]);
            float4 t0 = tbl[8 * nt + 2 * c];
            float4 t1 = tbl[8 * nt + 2 * c + 1];
            float h;
            h = fmaxf(acc[0] + t0.x, 0.0f);
            pa0 = fmaf(h, t0.y, pa0); pb0 = fmaf(h, t0.z, pb0);
            h = fmaxf(acc[1] + t1.x, 0.0f);
            pa0 = fmaf(h, t1.y, pa0); pb0 = fmaf(h, t1.z, pb0);
            h = fmaxf(acc[2] + t0.x, 0.0f);
            pa1 = fmaf(h, t0.y, pa1); pb1 = fmaf(h, t0.z, pb1);
            h = fmaxf(acc[3] + t1.x, 0.0f);
            pa1 = fmaf(h, t1.y, pa1); pb1 = fmaf(h, t1.z, pb1);
        }

        // ---- quad reduce: all 4 lanes of quad get full (a,b) of both edges ----
        pa0 += __shfl_xor_sync(FULL, pa0, 1); pa0 += __shfl_xor_sync(FULL, pa0, 2);
        pb0 += __shfl_xor_sync(FULL, pb0, 1); pb0 += __shfl_xor_sync(FULL, pb0, 2);
        pa1 += __shfl_xor_sync(FULL, pa1, 1); pa1 += __shfl_xor_sync(FULL, pa1, 2);
        pb1 += __shfl_xor_sync(FULL, pb1, 1); pb1 += __shfl_xor_sync(FULL, pb1, 2);
        float aE0 = pa0 + b2v.x, bE0 = pb0 + b2v.y;
        float aE1 = pa1 + b2v.x, bE1 = pb1 + b2v.y;

        // ---- epilogue straight from A-frag registers ----
        float2 xd, xs, o;
        // e0, cols 2c,2c+1
        xd = __half22float2(*(__half2*)&ad0);
        xs = __half22float2(*(__half2*)&as0);
        o.x = aE0 * (xd.x - bE0 * xs.x);
        o.y = aE0 * (xd.y - bE0 * xs.y);
        *(float2*)(out + e0 * FF + 2 * c) = o;
        // e0, cols 8+2c,8+2c+1
        xd = __half22float2(*(__half2*)&ad2);
        xs = __half22float2(*(__half2*)&as2);
        o.x = aE0 * (xd.x - bE0 * xs.x);
        o.y = aE0 * (xd.y - bE0 * xs.y);
        *(float2*)(out + e0 * FF + 8 + 2 * c) = o;
        // e1, cols 2c,2c+1
        xd = __half22float2(*(__half2*)&ad1);
        xs = __half22float2(*(__half2*)&as1);
        o.x = aE1 * (xd.x - bE1 * xs.x);
        o.y = aE1 * (xd.y - bE1 * xs.y);
        *(float2*)(out + e1 * FF + 2 * c) = o;
        // e1, cols 8+2c,8+2c+1
        xd = __half22float2(*(__half2*)&ad3);
        xs = __half22float2(*(__half2*)&as3);
        o.x = aE1 * (xd.x - bE1 * xs.x);
        o.y = aE1 * (xd.y - bE1 * xs.y);
        *(float2*)(out + e1 * FF + 8 + 2 * c) = o;
    }
}

// ---------------------------------------------------------------------------
// Launch
// ---------------------------------------------------------------------------
extern "C" void kernel_launch(void* const* d_in, const int* in_sizes, int n_in,
                              void* d_out, int out_size)
{
    const float* x   = (const float*)d_in[0];   // [N,16]
    const int*   ei  = (const int*)d_in[1];     // [2,E] int32
    const float* W1  = (const float*)d_in[2];   // [32,64]
    const float* b1  = (const float*)d_in[3];   // [64]
    const float* W2  = (const float*)d_in[4];   // [64,2]
    const float* b2  = (const float*)d_in[5];   // [2]
    float*       out = (float*)d_out;           // [E,16]

    (void)in_sizes; (void)n_in; (void)out_size;

    convert_kernel<<<(NN * 2 + 255) / 256, 256>>>(x);
    edge_mma_kernel<<<GRID_MMA, 128>>>(ei, W1, b1, W2, b2, out);
}